// round 9
// baseline (speedup 1.0000x reference)
#include <cuda_runtime.h>
#include <cstdint>
#include <math.h>

#define TOKENS 16384
#define KDIM   2048
#define NEXP   64
#define TM     64                      // tokens per CTA -> grid 256 (all resident at occ 2)
#define KC     64                      // K elems per chunk
#define NCHUNK (KDIM / KC)             // 32
#define SA     144                     // smem row stride bytes (conflict-free ldmatrix)
#define OFF_B  (64 * SA)               // 9216
#define STAGE  (2 * 64 * SA)           // 18432 per stage (A 64x64 fp16 + B 64x64 fp16)
#define NSTAGE 3
#define DYN_SMEM (NSTAGE * STAGE)      // 55296 -> 2 CTAs/SM
#define RESCUE_TH 1.5e-3f

typedef unsigned int u32;

// Pre-converted W fp16 plane (pairs packed in u32), refreshed every call.
__device__ __align__(16) u32 g_Wh[NEXP * KDIM / 2];

// ---------------- helpers ----------------
static __device__ __forceinline__ u32 smem_u32(const void* p) {
    u32 a;
    asm("{ .reg .u64 t; cvta.to.shared.u64 t, %1; cvt.u32.u64 %0, t; }" : "=r"(a) : "l"(p));
    return a;
}
static __device__ __forceinline__ u32 cvt_h2(float f0, float f1) {
    u32 r;
    asm("cvt.rn.f16x2.f32 %0, %1, %2;" : "=r"(r) : "f"(f1), "f"(f0));
    return r;
}
static __device__ __forceinline__ void sts64(u32 a, u32 lo, u32 hi) {
    asm volatile("st.shared.v2.b32 [%0], {%1,%2};" :: "r"(a), "r"(lo), "r"(hi) : "memory");
}
static __device__ __forceinline__ void cpasync16(u32 dst, const void* src) {
    asm volatile("cp.async.cg.shared.global [%0], [%1], 16;" :: "r"(dst), "l"(src) : "memory");
}
#define CP_COMMIT() asm volatile("cp.async.commit_group;" ::: "memory")
#define CP_WAIT0()  asm volatile("cp.async.wait_group 0;" ::: "memory")
#define CP_WAIT1()  asm volatile("cp.async.wait_group 1;" ::: "memory")
static __device__ __forceinline__ void ldm_x4(u32* r, u32 a) {
    asm volatile("ldmatrix.sync.aligned.m8n8.x4.shared.b16 {%0,%1,%2,%3}, [%4];"
                 : "=r"(r[0]), "=r"(r[1]), "=r"(r[2]), "=r"(r[3]) : "r"(a));
}
static __device__ __forceinline__ void mma_f16(float* c, const u32* a, const u32* b) {
    asm volatile("mma.sync.aligned.m16n8k16.row.col.f32.f16.f16.f32 "
                 "{%0,%1,%2,%3}, {%4,%5,%6,%7}, {%8,%9}, {%0,%1,%2,%3};"
                 : "+f"(c[0]), "+f"(c[1]), "+f"(c[2]), "+f"(c[3])
                 : "r"(a[0]), "r"(a[1]), "r"(a[2]), "r"(a[3]), "r"(b[0]), "r"(b[1]));
}

// ---------------- W fp16 prep kernel ----------------
__global__ void prep_w(const float* __restrict__ W) {
    int p = blockIdx.x * blockDim.x + threadIdx.x;   // pair index, 65536 total
    float2 xy = ((const float2*)W)[p];
    g_Wh[p] = cvt_h2(xy.x, xy.y);
}

// ---------------- exact fp32 rescoring ----------------
__device__ __noinline__ float exact_dot(const float* __restrict__ xr, const float* __restrict__ wr) {
    float a0 = 0.f, a1 = 0.f, a2 = 0.f, a3 = 0.f;
    for (int k = 0; k < KDIM; k += 4) {
        a0 = fmaf(__ldg(xr + k + 0), __ldg(wr + k + 0), a0);
        a1 = fmaf(__ldg(xr + k + 1), __ldg(wr + k + 1), a1);
        a2 = fmaf(__ldg(xr + k + 2), __ldg(wr + k + 2), a2);
        a3 = fmaf(__ldg(xr + k + 3), __ldg(wr + k + 3), a3);
    }
    return (a0 + a1) + (a2 + a3);
}

// ---------------- main kernel ----------------
__global__ __launch_bounds__(256, 2)
void router_mma(const float* __restrict__ x,
                const float* __restrict__ W,
                const float* __restrict__ bias,
                float* __restrict__ out)
{
    extern __shared__ __align__(16) char dsmp[];
    const u32 sb = smem_u32(dsmp);
    __shared__ float s_bias[NEXP];

    const int tid  = threadIdx.x;
    const int wid  = tid >> 5;
    const int lane = tid & 31;
    const int wm   = wid & 1;          // M block (32 tokens)
    const int wn   = wid >> 1;         // N block (16 experts)
    const int tokBase = blockIdx.x * TM;

    if (tid < NEXP) s_bias[tid] = bias[tid];

    float acc[2][2][4];                // [mt m16][nt n8][frag]
#pragma unroll
    for (int i = 0; i < 2; i++)
#pragma unroll
        for (int j = 0; j < 2; j++)
#pragma unroll
            for (int q = 0; q < 4; q++) acc[i][j][q] = 0.f;

    float4 px0[4], px1[4];             // ping-pong x prefetch (2-chunk lookahead)
    const float4* xp = (const float4*)x;
    const uint4* whp = (const uint4*)g_Wh;

    // fixed load mappings
    const int xrow = tid >> 4, xc4 = tid & 15;      // x: slot s=tid+256r -> row (tid>>4)+16r, col tid&15
    const int brow = tid >> 3, bc16 = tid & 7;      // B: rows tid>>3, +32

#define LOAD_PX(P, c)                                                               \
    {                                                                               \
        _Pragma("unroll")                                                           \
        for (int r = 0; r < 4; r++)                                                 \
            P[r] = xp[(size_t)(tokBase + xrow + r * 16) * (KDIM / 4) + (c) * 16 + xc4]; \
    }

#define ISSUE_B(c, st)                                                              \
    {                                                                               \
        _Pragma("unroll")                                                           \
        for (int r = 0; r < 2; r++) {                                               \
            int row = brow + r * 32;                                                \
            cpasync16(sb + (u32)(st) * STAGE + OFF_B + (u32)(row * SA + bc16 * 16), \
                      whp + row * (KDIM / 8) + (c) * 8 + bc16);                     \
        }                                                                           \
        CP_COMMIT();                                                                \
    }

#define STS_A(P, st)                                                                \
    {                                                                               \
        _Pragma("unroll")                                                           \
        for (int r = 0; r < 4; r++) {                                               \
            u32 a = sb + (u32)(st) * STAGE + (u32)((xrow + r * 16) * SA + xc4 * 8); \
            float4 v = P[r];                                                        \
            sts64(a, cvt_h2(v.x, v.y), cvt_h2(v.z, v.w));                           \
        }                                                                           \
    }

    // consumer base offsets (stage-relative)
    const u32 aOff = (u32)((wm * 32 + (lane & 15)) * SA + (lane >> 4) * 16);
    const u32 bOff = (u32)(OFF_B + (wn * 16 + ((lane >> 4) & 1) * 8 + (lane & 7)) * SA +
                           ((lane >> 3) & 1) * 16);

    // ---------------- prologue ----------------
    ISSUE_B(0, 0);
    ISSUE_B(1, 1);
    LOAD_PX(px0, 0);
    LOAD_PX(px1, 1);
    STS_A(px0, 0);                 // waits on px0 DRAM latency once
    LOAD_PX(px0, 2);

    // ---------------- main loop (fully scripted stages) ----------------
    // iter c: stage cur=c%3 holds A(c)+B(c); B(c+1) in flight to (c+1)%3;
    //         px[(c+1)&1] holds A(c+1) raw; px[(c+2)&1... ] chunk c+2 in flight.
#pragma unroll
    for (int c = 0; c < NCHUNK; c++) {
        const int cur = c % 3;
        const int st1 = (c + 1) % 3;
        const int st2 = (c + 2) % 3;
        if (c == NCHUNK - 1) { CP_WAIT0(); } else { CP_WAIT1(); }
        __syncthreads();               // A(c)+B(c) visible; stage st2 (== (c-1)%3) free

        const u32 aAddr = sb + (u32)cur * STAGE + aOff;
        const u32 bAddr = sb + (u32)cur * STAGE + bOff;
#pragma unroll
        for (int ks = 0; ks < 4; ks++) {
            const u32 kb = ks * 32;
            u32 A[2][4], B[4];
            ldm_x4(A[0], aAddr + kb);
            ldm_x4(A[1], aAddr + 16 * SA + kb);
            ldm_x4(B, bAddr + kb);
#pragma unroll
            for (int mt = 0; mt < 2; mt++)
#pragma unroll
                for (int nt = 0; nt < 2; nt++)
                    mma_f16(acc[mt][nt], A[mt], &B[nt * 2]);
        }

        if (c & 1) {
            if (c + 1 < NCHUNK) STS_A(px0, st1);       // chunk c+1 raw in px0 (even)
            if (c + 2 < NCHUNK) ISSUE_B(c + 2, st2);
            if (c + 3 < NCHUNK) LOAD_PX(px0, c + 3);   // px0 freed by STS above
        } else {
            if (c + 1 < NCHUNK) STS_A(px1, st1);       // chunk c+1 raw in px1 (odd)
            if (c + 2 < NCHUNK) ISSUE_B(c + 2, st2);
            if (c + 3 < NCHUNK) LOAD_PX(px1, c + 3);
        }
    }

    // ---------------- epilogue ----------------
    __syncthreads();
    float* ls = (float*)dsmp;            // logits staging [64][65]; stage mem dead
#pragma unroll
    for (int mt = 0; mt < 2; mt++)
#pragma unroll
        for (int nt = 0; nt < 2; nt++) {
            const int row = wm * 32 + mt * 16 + (lane >> 2);
            const int col = wn * 16 + nt * 8 + (lane & 3) * 2;
            ls[row * 65 + col]           = acc[mt][nt][0] + s_bias[col];
            ls[row * 65 + col + 1]       = acc[mt][nt][1] + s_bias[col + 1];
            ls[(row + 8) * 65 + col]     = acc[mt][nt][2] + s_bias[col];
            ls[(row + 8) * 65 + col + 1] = acc[mt][nt][3] + s_bias[col + 1];
        }
    __syncthreads();

    float* probs_out  = out;
    float* idx_out    = out + (size_t)TOKENS * 2;
    float* logits_out = out + (size_t)TOKENS * 4;

    // coalesced logits store: 1024 float4 per block, 4 per thread
#pragma unroll
    for (int r = 0; r < 4; r++) {
        int s  = tid + 256 * r;
        int t  = s >> 4;
        int e4 = s & 15;
        const float* lr = &ls[t * 65 + e4 * 4];
        *(float4*)(logits_out + (size_t)(tokBase + t) * NEXP + e4 * 4) =
            make_float4(lr[0], lr[1], lr[2], lr[3]);
    }

    // top-2 + softmax (+ exact rescue): one thread per token
    if (tid < TM) {
        const int t = tid;
        const int gt = tokBase + t;
        const float* lr = &ls[t * 65];
        float m1 = -INFINITY, m2 = -INFINITY, m3 = -INFINITY;
        int i1 = 0, i2 = 0;
#pragma unroll
        for (int e = 0; e < NEXP; e++) {
            const float v = lr[e];
            if (v > m1)      { m3 = m2; m2 = m1; i2 = i1; m1 = v; i1 = e; }
            else if (v > m2) { m3 = m2; m2 = v; i2 = e; }
            else if (v > m3) { m3 = v; }
        }
        float p1v = m1, p2v = m2;

        if ((m1 - m2 < RESCUE_TH) || (m2 - m3 < RESCUE_TH)) {
            const float thr = m2 - RESCUE_TH;
            float e1 = -INFINITY, e2 = -INFINITY;
            int j1 = 0, j2 = 0;
            const float* xr = x + (size_t)gt * KDIM;
#pragma unroll 1
            for (int e = 0; e < NEXP; e++) {
                if (lr[e] > thr) {
                    float ex = exact_dot(xr, W + (size_t)e * KDIM) + s_bias[e];
                    if (ex > e1)      { e2 = e1; j2 = j1; e1 = ex; j1 = e; }
                    else if (ex > e2) { e2 = ex; j2 = e; }
                }
            }
            i1 = j1; i2 = j2; p1v = e1; p2v = e2;
        }

        const float ex2 = expf(p2v - p1v);
        const float inv = 1.0f / (1.0f + ex2);
        probs_out[gt * 2 + 0] = inv;
        probs_out[gt * 2 + 1] = ex2 * inv;
        idx_out[gt * 2 + 0] = (float)i1;
        idx_out[gt * 2 + 1] = (float)i2;
    }
}

extern "C" void kernel_launch(void* const* d_in, const int* in_sizes, int n_in,
                              void* d_out, int out_size)
{
    const float* x = (const float*)d_in[0];
    const float* W = (const float*)d_in[1];
    const float* b = (const float*)d_in[2];
    float* out = (float*)d_out;

    cudaFuncSetAttribute(router_mma, cudaFuncAttributeMaxDynamicSharedMemorySize, DYN_SMEM);
    prep_w<<<256, 256>>>(W);
    router_mma<<<TOKENS / TM, 256, DYN_SMEM>>>(x, W, b, out);
}

// round 10
// speedup vs baseline: 5.1535x; 5.1535x over previous
#include <cuda_runtime.h>
#include <cstdint>
#include <math.h>

#define TOKENS 16384
#define KDIM   2048
#define NEXP   64
#define TM     64                      // tokens per CTA -> grid 256 (all resident at occ 2)
#define KC     64                      // K elems per chunk
#define NCHUNK (KDIM / KC)             // 32
#define SA     144                     // smem row stride bytes (conflict-free ldmatrix)
#define OFF_B  (64 * SA)               // 9216
#define STAGE  (2 * 64 * SA)           // 18432 per stage
#define NSTAGE 3
#define DYN_SMEM (NSTAGE * STAGE)      // 55296 -> 2 CTAs/SM
#define RESCUE_TH 2.5e-3f

typedef unsigned int u32;

// Pre-converted W fp16 plane (pairs packed in u32), refreshed every call.
__device__ __align__(16) u32 g_Wh[NEXP * KDIM / 2];

// ---------------- helpers ----------------
static __device__ __forceinline__ u32 smem_u32(const void* p) {
    u32 a;
    asm("{ .reg .u64 t; cvta.to.shared.u64 t, %1; cvt.u32.u64 %0, t; }" : "=r"(a) : "l"(p));
    return a;
}
static __device__ __forceinline__ u32 cvt_h2(float f0, float f1) {
    u32 r;
    asm("cvt.rn.f16x2.f32 %0, %1, %2;" : "=r"(r) : "f"(f1), "f"(f0));
    return r;
}
static __device__ __forceinline__ void sts64(u32 a, u32 lo, u32 hi) {
    asm volatile("st.shared.v2.b32 [%0], {%1,%2};" :: "r"(a), "r"(lo), "r"(hi) : "memory");
}
static __device__ __forceinline__ void cpasync16(u32 dst, const void* src) {
    asm volatile("cp.async.cg.shared.global [%0], [%1], 16;" :: "r"(dst), "l"(src) : "memory");
}
#define CP_COMMIT() asm volatile("cp.async.commit_group;" ::: "memory")
#define CP_WAIT0()  asm volatile("cp.async.wait_group 0;" ::: "memory")
#define CP_WAIT1()  asm volatile("cp.async.wait_group 1;" ::: "memory")
static __device__ __forceinline__ void ldm_x4(u32* r, u32 a) {
    asm volatile("ldmatrix.sync.aligned.m8n8.x4.shared.b16 {%0,%1,%2,%3}, [%4];"
                 : "=r"(r[0]), "=r"(r[1]), "=r"(r[2]), "=r"(r[3]) : "r"(a));
}
static __device__ __forceinline__ void mma_f16(float* c, const u32* a, const u32* b) {
    asm volatile("mma.sync.aligned.m16n8k16.row.col.f32.f16.f16.f32 "
                 "{%0,%1,%2,%3}, {%4,%5,%6,%7}, {%8,%9}, {%0,%1,%2,%3};"
                 : "+f"(c[0]), "+f"(c[1]), "+f"(c[2]), "+f"(c[3])
                 : "r"(a[0]), "r"(a[1]), "r"(a[2]), "r"(a[3]), "r"(b[0]), "r"(b[1]));
}

// ---------------- W fp16 prep kernel ----------------
__global__ void prep_w(const float* __restrict__ W) {
    int p = blockIdx.x * blockDim.x + threadIdx.x;   // pair index, 65536 total
    float2 xy = ((const float2*)W)[p];
    g_Wh[p] = cvt_h2(xy.x, xy.y);
}

// ---------------- warp-cooperative exact fp32 dot ----------------
// 32 lanes: lane l covers elements {l*4 + 128*i + j}, i<16, j<4  (coalesced float4)
static __device__ __forceinline__ float warp_dot(const float4* __restrict__ xr4,
                                                 const float4* __restrict__ wr4,
                                                 int lane) {
    float a0 = 0.f, a1 = 0.f, a2 = 0.f, a3 = 0.f;
#pragma unroll
    for (int i = 0; i < 16; i++) {
        float4 xv = __ldg(xr4 + lane + 32 * i);
        float4 wv = __ldg(wr4 + lane + 32 * i);
        a0 = fmaf(xv.x, wv.x, a0);
        a1 = fmaf(xv.y, wv.y, a1);
        a2 = fmaf(xv.z, wv.z, a2);
        a3 = fmaf(xv.w, wv.w, a3);
    }
    float s = (a0 + a1) + (a2 + a3);
#pragma unroll
    for (int o = 16; o > 0; o >>= 1)
        s += __shfl_xor_sync(0xffffffffu, s, o);
    return s;
}

// ---------------- main kernel ----------------
__global__ __launch_bounds__(256, 2)
void router_mma(const float* __restrict__ x,
                const float* __restrict__ W,
                const float* __restrict__ bias,
                float* __restrict__ out)
{
    extern __shared__ __align__(16) char dsmp[];
    const u32 sb = smem_u32(dsmp);
    __shared__ float s_bias[NEXP];
    __shared__ int   s_cnt;
    __shared__ int   s_list[TM];
    __shared__ float s_thr[TM];

    const int tid  = threadIdx.x;
    const int wid  = tid >> 5;
    const int lane = tid & 31;
    const int wm   = wid & 1;          // M block (32 tokens)
    const int wn   = wid >> 1;         // N block (16 experts)
    const int tokBase = blockIdx.x * TM;

    if (tid < NEXP) s_bias[tid] = bias[tid];
    if (tid == 0) s_cnt = 0;

    float acc[2][2][4];
#pragma unroll
    for (int i = 0; i < 2; i++)
#pragma unroll
        for (int j = 0; j < 2; j++)
#pragma unroll
            for (int q = 0; q < 4; q++) acc[i][j][q] = 0.f;

    float4 px0[4], px1[4];             // ping-pong x prefetch (2-chunk lookahead)
    const float4* xp = (const float4*)x;
    const uint4* whp = (const uint4*)g_Wh;

    const int xrow = tid >> 4, xc4 = tid & 15;
    const int brow = tid >> 3, bc16 = tid & 7;

#define LOAD_PX(P, c)                                                               \
    {                                                                               \
        _Pragma("unroll")                                                           \
        for (int r = 0; r < 4; r++)                                                 \
            P[r] = xp[(size_t)(tokBase + xrow + r * 16) * (KDIM / 4) + (c) * 16 + xc4]; \
    }

#define ISSUE_B(c, st)                                                              \
    {                                                                               \
        _Pragma("unroll")                                                           \
        for (int r = 0; r < 2; r++) {                                               \
            int row = brow + r * 32;                                                \
            cpasync16(sb + (u32)(st) * STAGE + OFF_B + (u32)(row * SA + bc16 * 16), \
                      whp + row * (KDIM / 8) + (c) * 8 + bc16);                     \
        }                                                                           \
        CP_COMMIT();                                                                \
    }

#define STS_A(P, st)                                                                \
    {                                                                               \
        _Pragma("unroll")                                                           \
        for (int r = 0; r < 4; r++) {                                               \
            u32 a = sb + (u32)(st) * STAGE + (u32)((xrow + r * 16) * SA + xc4 * 8); \
            float4 v = P[r];                                                        \
            sts64(a, cvt_h2(v.x, v.y), cvt_h2(v.z, v.w));                           \
        }                                                                           \
    }

    const u32 aOff = (u32)((wm * 32 + (lane & 15)) * SA + (lane >> 4) * 16);
    const u32 bOff = (u32)(OFF_B + (wn * 16 + ((lane >> 4) & 1) * 8 + (lane & 7)) * SA +
                           ((lane >> 3) & 1) * 16);

    // ---------------- prologue ----------------
    ISSUE_B(0, 0);
    ISSUE_B(1, 1);
    LOAD_PX(px0, 0);
    LOAD_PX(px1, 1);
    STS_A(px0, 0);
    LOAD_PX(px0, 2);

    // ---------------- main loop ----------------
#pragma unroll
    for (int c = 0; c < NCHUNK; c++) {
        const int cur = c % 3;
        const int st1 = (c + 1) % 3;
        const int st2 = (c + 2) % 3;
        if (c == NCHUNK - 1) { CP_WAIT0(); } else { CP_WAIT1(); }
        __syncthreads();

        const u32 aAddr = sb + (u32)cur * STAGE + aOff;
        const u32 bAddr = sb + (u32)cur * STAGE + bOff;
#pragma unroll
        for (int ks = 0; ks < 4; ks++) {
            const u32 kb = ks * 32;
            u32 A[2][4], B[4];
            ldm_x4(A[0], aAddr + kb);
            ldm_x4(A[1], aAddr + 16 * SA + kb);
            ldm_x4(B, bAddr + kb);
#pragma unroll
            for (int mt = 0; mt < 2; mt++)
#pragma unroll
                for (int nt = 0; nt < 2; nt++)
                    mma_f16(acc[mt][nt], A[mt], &B[nt * 2]);
        }

        if (c & 1) {
            if (c + 1 < NCHUNK) STS_A(px0, st1);
            if (c + 2 < NCHUNK) ISSUE_B(c + 2, st2);
            if (c + 3 < NCHUNK) LOAD_PX(px0, c + 3);
        } else {
            if (c + 1 < NCHUNK) STS_A(px1, st1);
            if (c + 2 < NCHUNK) ISSUE_B(c + 2, st2);
            if (c + 3 < NCHUNK) LOAD_PX(px1, c + 3);
        }
    }

    // ---------------- epilogue ----------------
    __syncthreads();
    float* ls = (float*)dsmp;            // logits staging [64][65]
#pragma unroll
    for (int mt = 0; mt < 2; mt++)
#pragma unroll
        for (int nt = 0; nt < 2; nt++) {
            const int row = wm * 32 + mt * 16 + (lane >> 2);
            const int col = wn * 16 + nt * 8 + (lane & 3) * 2;
            ls[row * 65 + col]           = acc[mt][nt][0] + s_bias[col];
            ls[row * 65 + col + 1]       = acc[mt][nt][1] + s_bias[col + 1];
            ls[(row + 8) * 65 + col]     = acc[mt][nt][2] + s_bias[col];
            ls[(row + 8) * 65 + col + 1] = acc[mt][nt][3] + s_bias[col + 1];
        }
    __syncthreads();

    float* probs_out  = out;
    float* idx_out    = out + (size_t)TOKENS * 2;
    float* logits_out = out + (size_t)TOKENS * 4;

    // coalesced logits store: 1024 float4 per block, 4 per thread
#pragma unroll
    for (int r = 0; r < 4; r++) {
        int s  = tid + 256 * r;
        int t  = s >> 4;
        int e4 = s & 15;
        const float* lr = &ls[t * 65 + e4 * 4];
        *(float4*)(logits_out + (size_t)(tokBase + t) * NEXP + e4 * 4) =
            make_float4(lr[0], lr[1], lr[2], lr[3]);
    }

    // per-token top-2; near-ties enqueued for warp-parallel exact rescue
    if (tid < TM) {
        const int t = tid;
        const int gt = tokBase + t;
        const float* lr = &ls[t * 65];
        float m1 = -INFINITY, m2 = -INFINITY, m3 = -INFINITY;
        int i1 = 0, i2 = 0;
#pragma unroll
        for (int e = 0; e < NEXP; e++) {
            const float v = lr[e];
            if (v > m1)      { m3 = m2; m2 = m1; i2 = i1; m1 = v; i1 = e; }
            else if (v > m2) { m3 = m2; m2 = v; i2 = e; }
            else if (v > m3) { m3 = v; }
        }

        if ((m1 - m2 < RESCUE_TH) || (m2 - m3 < RESCUE_TH)) {
            int j = atomicAdd(&s_cnt, 1);
            s_list[j] = t;
            s_thr[t]  = m2 - RESCUE_TH;
        } else {
            const float ex2 = expf(m2 - m1);
            const float inv = 1.0f / (1.0f + ex2);
            probs_out[gt * 2 + 0] = inv;
            probs_out[gt * 2 + 1] = ex2 * inv;
            idx_out[gt * 2 + 0] = (float)i1;
            idx_out[gt * 2 + 1] = (float)i2;
        }
    }
    __syncthreads();

    // warp-parallel exact rescue: each warp takes worklist entries round-robin
    const int cnt = s_cnt;
    for (int j = wid; j < cnt; j += 8) {
        const int t  = s_list[j];
        const int gt = tokBase + t;
        const float thr = s_thr[t];
        const float* lr = &ls[t * 65];
        const float4* xr4 = (const float4*)(x + (size_t)gt * KDIM);

        float e1 = -INFINITY, e2 = -INFINITY;
        int j1 = 0, j2 = 0;
        for (int e = 0; e < NEXP; e++) {          // ascending: jax first-index tie-break
            if (lr[e] > thr) {                    // warp-uniform (smem broadcast)
                const float4* wr4 = (const float4*)(W + (size_t)e * KDIM);
                float ex = warp_dot(xr4, wr4, lane) + s_bias[e];
                if (ex > e1)      { e2 = e1; j2 = j1; e1 = ex; j1 = e; }
                else if (ex > e2) { e2 = ex; j2 = e; }
            }
        }
        if (lane == 0) {
            const float ex2 = expf(e2 - e1);
            const float inv = 1.0f / (1.0f + ex2);
            probs_out[gt * 2 + 0] = inv;
            probs_out[gt * 2 + 1] = ex2 * inv;
            idx_out[gt * 2 + 0] = (float)j1;
            idx_out[gt * 2 + 1] = (float)j2;
        }
    }
}

extern "C" void kernel_launch(void* const* d_in, const int* in_sizes, int n_in,
                              void* d_out, int out_size)
{
    const float* x = (const float*)d_in[0];
    const float* W = (const float*)d_in[1];
    const float* b = (const float*)d_in[2];
    float* out = (float*)d_out;

    cudaFuncSetAttribute(router_mma, cudaFuncAttributeMaxDynamicSharedMemorySize, DYN_SMEM);
    prep_w<<<256, 256>>>(W);
    router_mma<<<TOKENS / TM, 256, DYN_SMEM>>>(x, W, b, out);
}